// round 9
// baseline (speedup 1.0000x reference)
#include <cuda_runtime.h>
#include <cuda_fp16.h>
#include <stdint.h>

#define NS 32
#define TT 2048
#define ND 1024
#define GRID 128
#define NTHREADS 256
#define NWARPS 8
#define KTILES 8     // 8 warps * 8 ktiles * 16 = 1024 = K
#define ROWBLK 32    // A rows per CTA
#define SBLK 8       // samples per CTA
#define SGROUPS 4
#define NCHUNK ((TT - 2) / 3)   // 682 three-step chunks, then 1 single step

#define ALPHA 0.1f
#define BETA  0.9f
#define A2C   (ALPHA * ALPHA)    // 0.01
#define ABC   (ALPHA * BETA)     // 0.09
#define BB    (BETA * BETA)      // 0.81
#define AB2   (2.0f * ALPHA * BETA) // 0.18

// Double-buffered fp16 hidden state, pre-swizzled mma-B layout.
__device__ __align__(16) __half g_hbuf[2][NS * ND];
// A@A and A@A@A (row-major fp32), computed once per launch.
__device__ float g_A2[ND * ND];
__device__ float g_A3[ND * ND];
// Producer flags: g_flags[sb][rb] = completed productions by CTA (rb, sb).
__device__ __align__(256) volatile unsigned g_flags[SGROUPS][32];
// Sense-reversing grid barrier (phase transitions + cleanup only).
__device__ unsigned g_bar_count;
__device__ unsigned g_bar_gen;

__device__ __forceinline__ void grid_barrier() {
    __syncthreads();
    if (threadIdx.x == 0) {
        unsigned gen = *((volatile unsigned*)&g_bar_gen);
        __threadfence();
        unsigned old = atomicAdd(&g_bar_count, 1u);
        if (old == GRID - 1) {
            g_bar_count = 0;
            __threadfence();
            atomicExch(&g_bar_gen, gen + 1u);
        } else {
            while (*((volatile unsigned*)&g_bar_gen) == gen) { }
        }
        __threadfence();
    }
    __syncthreads();
}

__device__ __forceinline__ void mma16816(float* d, const uint32_t* a,
                                         uint32_t b0, uint32_t b1) {
    asm volatile(
        "mma.sync.aligned.m16n8k16.row.col.f32.f16.f16.f32 "
        "{%0,%1,%2,%3}, {%4,%5,%6,%7}, {%8,%9}, {%0,%1,%2,%3};\n"
        : "+f"(d[0]), "+f"(d[1]), "+f"(d[2]), "+f"(d[3])
        : "r"(a[0]), "r"(a[1]), "r"(a[2]), "r"(a[3]), "r"(b0), "r"(b1));
}

// Swizzled position of logical element j (per 16-block order 0,1,8,9,2,3,...).
__device__ __forceinline__ int hpos(int j) {
    int r = j & 15;
    return (j & ~15) + ((r & 6) << 1) + ((r >> 3) << 1) + (r & 1);
}

__device__ __forceinline__ unsigned flag_acquire(const volatile unsigned* p) {
    unsigned v;
    asm volatile("ld.global.acquire.gpu.u32 %0, [%1];"
                 : "=r"(v) : "l"((const unsigned*)p) : "memory");
    return v;
}

__device__ __forceinline__ void flag_release(volatile unsigned* p, unsigned v) {
    asm volatile("st.global.release.gpu.u32 [%0], %1;"
                 :: "l"((unsigned*)p), "r"(v) : "memory");
}

__device__ __forceinline__ void prefetch_l2(const void* p) {
    asm volatile("prefetch.global.L2 [%0];" :: "l"(p));
}

__device__ __forceinline__ void load_afrag(uint32_t* f, const float* src,
                                           int row, int k0) {
    const float* p = src + (size_t)row * ND + k0;
    float2 v0 = *(const float2*)(p);
    float2 v1 = *(const float2*)(p + 8 * (size_t)ND);
    float2 v2 = *(const float2*)(p + 8);
    float2 v3 = *(const float2*)(p + 8 * (size_t)ND + 8);
    __half2 q0 = __floats2half2_rn(v0.x, v0.y);
    __half2 q1 = __floats2half2_rn(v1.x, v1.y);
    __half2 q2 = __floats2half2_rn(v2.x, v2.y);
    __half2 q3 = __floats2half2_rn(v3.x, v3.y);
    f[0] = *(uint32_t*)&q0; f[1] = *(uint32_t*)&q1;
    f[2] = *(uint32_t*)&q2; f[3] = *(uint32_t*)&q3;
}

__global__ __launch_bounds__(NTHREADS, 1) void rnn_kernel(
    const float* __restrict__ inp,   // [NS, TT, ND]
    const float* __restrict__ A,     // [ND, ND]
    const float* __restrict__ h0,    // [NS, ND]
    float* __restrict__ out)         // [NS, TT, ND]
{
    // Static SMEM: 4 psum arrays (P1, R2, R3, Q4) = 32 KB.
    __shared__ float psum[4][NWARPS][SBLK * ROWBLK];
    // Dynamic SMEM: A^3 fragments, 64 KB, per-warp frag layout.
    extern __shared__ uint4 smemA3[];

    const int tid  = threadIdx.x;
    const int w    = tid >> 5;
    const int lane = tid & 31;
    const int g    = lane >> 2;
    const int tig  = lane & 3;

    const int cta  = blockIdx.x;
    const int rb   = cta >> 2;        // 32 row blocks
    const int sb   = cta & 3;         // 4 sample groups
    const int row0 = rb * ROWBLK;
    const int s0   = sb * SBLK;

    // ---- Resident A fragments (k-split across warps) ----
    uint32_t afrag[KTILES][2][4];
#pragma unroll
    for (int kt = 0; kt < KTILES; kt++) {
        int k0 = (w * KTILES + kt) * 16 + 2 * tig;
        load_afrag(afrag[kt][0], A, row0 + g, k0);
        load_afrag(afrag[kt][1], A, row0 + 16 + g, k0);
    }

    // ========== Phase 1a: A2 = A @ A (j-split by sb) ==========
    for (int jj = 0; jj < 32; jj++) {
        const int jblk = sb * 32 + jj;
        const int j    = jblk * 8 + g;
        float d[2][4];
#pragma unroll
        for (int m = 0; m < 2; m++)
#pragma unroll
            for (int c = 0; c < 4; c++) d[m][c] = 0.0f;
#pragma unroll
        for (int kt = 0; kt < KTILES; kt++) {
            const int kb = (w * KTILES + kt) * 16;
            float e0 = A[(size_t)(kb + 2 * tig)     * ND + j];
            float e1 = A[(size_t)(kb + 2 * tig + 1) * ND + j];
            float e2 = A[(size_t)(kb + 2 * tig + 8) * ND + j];
            float e3 = A[(size_t)(kb + 2 * tig + 9) * ND + j];
            __half2 hb0 = __floats2half2_rn(e0, e1);
            __half2 hb1 = __floats2half2_rn(e2, e3);
            mma16816(d[0], afrag[kt][0], *(uint32_t*)&hb0, *(uint32_t*)&hb1);
            mma16816(d[1], afrag[kt][1], *(uint32_t*)&hb0, *(uint32_t*)&hb1);
        }
#pragma unroll
        for (int m = 0; m < 2; m++)
#pragma unroll
            for (int c = 0; c < 4; c++) {
                int i_loc = m * 16 + g + ((c >> 1) << 3);
                int j_loc = tig * 2 + (c & 1);
                psum[0][w][j_loc * ROWBLK + i_loc] = d[m][c];
            }
        __syncthreads();
        {
            int i_loc = tid & 31;
            int j_loc = tid >> 5;
            float s = 0.f;
#pragma unroll
            for (int ww = 0; ww < NWARPS; ww++)
                s += psum[0][ww][j_loc * ROWBLK + i_loc];
            g_A2[(size_t)(row0 + i_loc) * ND + jblk * 8 + j_loc] = s;
        }
        __syncthreads();
    }
    grid_barrier();

    // ---- Resident A^2 fragments ----
    uint32_t a2frag[KTILES][2][4];
#pragma unroll
    for (int kt = 0; kt < KTILES; kt++) {
        int k0 = (w * KTILES + kt) * 16 + 2 * tig;
        load_afrag(a2frag[kt][0], g_A2, row0 + g, k0);
        load_afrag(a2frag[kt][1], g_A2, row0 + 16 + g, k0);
    }

    // ========== Phase 1b: A3 = A2 @ A (same structure) ==========
    for (int jj = 0; jj < 32; jj++) {
        const int jblk = sb * 32 + jj;
        const int j    = jblk * 8 + g;
        float d[2][4];
#pragma unroll
        for (int m = 0; m < 2; m++)
#pragma unroll
            for (int c = 0; c < 4; c++) d[m][c] = 0.0f;
#pragma unroll
        for (int kt = 0; kt < KTILES; kt++) {
            const int kb = (w * KTILES + kt) * 16;
            float e0 = A[(size_t)(kb + 2 * tig)     * ND + j];
            float e1 = A[(size_t)(kb + 2 * tig + 1) * ND + j];
            float e2 = A[(size_t)(kb + 2 * tig + 8) * ND + j];
            float e3 = A[(size_t)(kb + 2 * tig + 9) * ND + j];
            __half2 hb0 = __floats2half2_rn(e0, e1);
            __half2 hb1 = __floats2half2_rn(e2, e3);
            mma16816(d[0], a2frag[kt][0], *(uint32_t*)&hb0, *(uint32_t*)&hb1);
            mma16816(d[1], a2frag[kt][1], *(uint32_t*)&hb0, *(uint32_t*)&hb1);
        }
#pragma unroll
        for (int m = 0; m < 2; m++)
#pragma unroll
            for (int c = 0; c < 4; c++) {
                int i_loc = m * 16 + g + ((c >> 1) << 3);
                int j_loc = tig * 2 + (c & 1);
                psum[0][w][j_loc * ROWBLK + i_loc] = d[m][c];
            }
        __syncthreads();
        {
            int i_loc = tid & 31;
            int j_loc = tid >> 5;
            float s = 0.f;
#pragma unroll
            for (int ww = 0; ww < NWARPS; ww++)
                s += psum[0][ww][j_loc * ROWBLK + i_loc];
            g_A3[(size_t)(row0 + i_loc) * ND + jblk * 8 + j_loc] = s;
        }
        __syncthreads();
    }
    grid_barrier();

    // ---- A^3 fragments into SMEM (each thread writes what it will read) ----
#pragma unroll
    for (int kt = 0; kt < KTILES; kt++) {
        int k0 = (w * KTILES + kt) * 16 + 2 * tig;
#pragma unroll
        for (int m = 0; m < 2; m++) {
            uint32_t tmp[4];
            load_afrag(tmp, g_A3, row0 + m * 16 + g, k0);
            smemA3[((w * KTILES + kt) * 2 + m) * 32 + lane] =
                make_uint4(tmp[0], tmp[1], tmp[2], tmp[3]);
        }
    }
    __syncthreads();

    // ---- Per-thread state ownership: 1 element each ----
    const int s_l  = tid >> 5;            // 0..7
    const int i_l  = tid & 31;            // 0..31
    const int s_gl = s0 + s_l;
    const int i_gl = row0 + i_l;
    const int e    = s_l * ROWBLK + i_l;

    const float* inp_base = inp + (size_t)s_gl * TT * ND + i_gl;
    float* out_base       = out + (size_t)s_gl * TT * ND + i_gl;
    const int hslot = s_gl * ND + hpos(i_gl);

    // Dedup prefetch: thread (tid&31)==rb covers line rb of 8 sample rows.
    const bool do_pf = ((tid & 31) == rb);
    const float* pf_base = inp + (size_t)(s0 + (tid >> 5)) * TT * ND + rb * 32;

    // ---- Production 0: h0 ----
    float hprev = h0[(size_t)s_gl * ND + i_gl];
    out_base[0] = hprev;
    g_hbuf[0][hslot] = __float2half_rn(hprev);
    __syncthreads();
    if (tid == 0) flag_release(&g_flags[sb][rb], 1u);

    if (do_pf) {
        prefetch_l2(pf_base);
        prefetch_l2(pf_base + ND);
        prefetch_l2(pf_base + 2 * (size_t)ND);
    }

    // x base for the Q GEMMs (B operand rows = samples s0+g).
    const float* xq_base = inp + (size_t)(s0 + g) * TT * ND;

    // ================= Main loop: 682 triple-steps =================
    for (int s = 0; s < NCHUNK; s++) {
        const int ts = 3 * s;   // consumes h[ts]; produces h[ts+1..ts+3]

        float xa = __ldcs(inp_base + (size_t)ts * ND);
        float xb = __ldcs(inp_base + (size_t)(ts + 1) * ND);
        float xc = __ldcs(inp_base + (size_t)(ts + 2) * ND);

        // Accumulators: P1 | R2=Q1+P2 | R3=Q2+P3 | Q4
        float p1a[2][4], r2a[2][4], r3a[2][4], q4a[2][4];
#pragma unroll
        for (int m = 0; m < 2; m++)
#pragma unroll
            for (int c = 0; c < 4; c++) {
                p1a[m][c] = 0.f; r2a[m][c] = 0.f;
                r3a[m][c] = 0.f; q4a[m][c] = 0.f;
            }

        // ---- Pre-wait: Q1 = A x_t, Q2 = A^2 x_t, Q4 = A(x_{t+1} - b x_t) ----
#pragma unroll
        for (int kt = 0; kt < KTILES; kt++) {
            int kb = (w * KTILES + kt) * 16 + 2 * tig;
            const float* xp = xq_base + (size_t)ts * ND + kb;
            const float* xn = xq_base + (size_t)(ts + 1) * ND + kb;
            float2 t0 = __ldcs((const float2*)xp);
            float2 t1 = __ldcs((const float2*)(xp + 8));
            float2 n0 = __ldcs((const float2*)xn);
            float2 n1 = __ldcs((const float2*)(xn + 8));
            __half2 ht0 = __floats2half2_rn(t0.x, t0.y);
            __half2 ht1 = __floats2half2_rn(t1.x, t1.y);
            __half2 hc0 = __floats2half2_rn(n0.x - BETA * t0.x, n0.y - BETA * t0.y);
            __half2 hc1 = __floats2half2_rn(n1.x - BETA * t1.x, n1.y - BETA * t1.y);
            uint32_t bt0 = *(uint32_t*)&ht0, bt1 = *(uint32_t*)&ht1;
            uint32_t bc0 = *(uint32_t*)&hc0, bc1 = *(uint32_t*)&hc1;
            mma16816(r2a[0], afrag[kt][0],  bt0, bt1);
            mma16816(r2a[1], afrag[kt][1],  bt0, bt1);
            mma16816(r3a[0], a2frag[kt][0], bt0, bt1);
            mma16816(r3a[1], a2frag[kt][1], bt0, bt1);
            mma16816(q4a[0], afrag[kt][0],  bc0, bc1);
            mma16816(q4a[1], afrag[kt][1],  bc0, bc1);
        }

        // Prefetch next chunk's 3 x rows (dedup across CTAs).
        if (do_pf && ts + 3 < TT) {
            prefetch_l2(pf_base + (size_t)(ts + 3) * ND);
            prefetch_l2(pf_base + (size_t)(ts + 4) * ND);
            prefetch_l2(pf_base + (size_t)(ts + 5) * ND);
        }

        // ---- Wait: warp 0 polls all 32 producers of this group ----
        if (w == 0) {
            const volatile unsigned* f = &g_flags[sb][lane];
            unsigned v = flag_acquire(f);
            while (__ballot_sync(0xffffffffu, v < (unsigned)(s + 1))) {
                if (v < (unsigned)(s + 1)) v = flag_acquire(f);
            }
        }
        __syncthreads();

        const __half* hb = g_hbuf[s & 1];

        // ---- Post-wait: P1 = A h, P2 += A^2 h, P3 += A^3 h ----
#pragma unroll
        for (int kt = 0; kt < KTILES; kt++) {
            int koff = (w * KTILES + kt) * 16 + tig * 4;
            uint2 b = *(const uint2*)(hb + (size_t)(s0 + g) * ND + koff);
            uint4 f0 = smemA3[((w * KTILES + kt) * 2 + 0) * 32 + lane];
            uint4 f1 = smemA3[((w * KTILES + kt) * 2 + 1) * 32 + lane];
            mma16816(p1a[0], afrag[kt][0],  b.x, b.y);
            mma16816(p1a[1], afrag[kt][1],  b.x, b.y);
            mma16816(r2a[0], a2frag[kt][0], b.x, b.y);
            mma16816(r2a[1], a2frag[kt][1], b.x, b.y);
            mma16816(r3a[0], (const uint32_t*)&f0, b.x, b.y);
            mma16816(r3a[1], (const uint32_t*)&f1, b.x, b.y);
        }

        // ---- cross-warp reduction (4 quantities) ----
#pragma unroll
        for (int m = 0; m < 2; m++)
#pragma unroll
            for (int c = 0; c < 4; c++) {
                int i_loc = m * 16 + g + ((c >> 1) << 3);
                int s_loc = tig * 2 + (c & 1);
                int slot = s_loc * ROWBLK + i_loc;
                psum[0][w][slot] = p1a[m][c];
                psum[1][w][slot] = r2a[m][c];
                psum[2][w][slot] = r3a[m][c];
                psum[3][w][slot] = q4a[m][c];
            }
        __syncthreads();

        float P1 = 0.f, R2 = 0.f, R3 = 0.f, Q4 = 0.f;
#pragma unroll
        for (int ww = 0; ww < NWARPS; ww++) {
            P1 += psum[0][ww][e];
            R2 += psum[1][ww][e];
            R3 += psum[2][ww][e];
            Q4 += psum[3][ww][e];
        }

        float h1  = BETA * hprev + ALPHA * (P1 + xa);
        float h2  = BETA * h1 + ABC * P1 + A2C * R2 + ALPHA * xb;
        float Ah2 = BB * P1 + AB2 * R2 + A2C * R3 + ALPHA * Q4;
        float h3  = BETA * h2 + ALPHA * (Ah2 + xc);
        hprev = h3;

        // Publish state first (critical path), outputs after the release.
        g_hbuf[(s + 1) & 1][hslot] = __float2half_rn(h3);
        __syncthreads();
        if (tid == 0) flag_release(&g_flags[sb][rb], (unsigned)(s + 2));

        __stcs(out_base + (size_t)(ts + 1) * ND, h1);
        __stcs(out_base + (size_t)(ts + 2) * ND, h2);
        __stcs(out_base + (size_t)(ts + 3) * ND, h3);
    }

    // ================= Epilogue: final single step t = TT-1 =================
    {
        const int s  = NCHUNK;          // 682: consumes h[2046]
        const int ts = 3 * s;           // 2046
        float xa = __ldcs(inp_base + (size_t)ts * ND);

        if (w == 0) {
            const volatile unsigned* f = &g_flags[sb][lane];
            unsigned v = flag_acquire(f);
            while (__ballot_sync(0xffffffffu, v < (unsigned)(s + 1))) {
                if (v < (unsigned)(s + 1)) v = flag_acquire(f);
            }
        }
        __syncthreads();

        const __half* hb = g_hbuf[s & 1];
        float d1[2][4];
#pragma unroll
        for (int m = 0; m < 2; m++)
#pragma unroll
            for (int c = 0; c < 4; c++) d1[m][c] = 0.f;

#pragma unroll
        for (int kt = 0; kt < KTILES; kt++) {
            int koff = (w * KTILES + kt) * 16 + tig * 4;
            uint2 b = *(const uint2*)(hb + (size_t)(s0 + g) * ND + koff);
            mma16816(d1[0], afrag[kt][0], b.x, b.y);
            mma16816(d1[1], afrag[kt][1], b.x, b.y);
        }
#pragma unroll
        for (int m = 0; m < 2; m++)
#pragma unroll
            for (int c = 0; c < 4; c++) {
                int i_loc = m * 16 + g + ((c >> 1) << 3);
                int s_loc = tig * 2 + (c & 1);
                psum[0][w][s_loc * ROWBLK + i_loc] = d1[m][c];
            }
        __syncthreads();

        float P1 = 0.f;
#pragma unroll
        for (int ww = 0; ww < NWARPS; ww++) P1 += psum[0][ww][e];

        float h1 = BETA * hprev + ALPHA * (P1 + xa);
        __stcs(out_base + (size_t)(ts + 1) * ND, h1);
    }

    // ---- Cleanup so graph replays start from flags == 0 ----
    grid_barrier();
    if (tid == 0) g_flags[sb][rb] = 0u;
}

extern "C" void kernel_launch(void* const* d_in, const int* in_sizes, int n_in,
                              void* d_out, int out_size) {
    const float* inp = (const float*)d_in[0];
    const float* A   = (const float*)d_in[1];
    const float* h0  = (const float*)d_in[2];
    float* out       = (float*)d_out;
    cudaFuncSetAttribute(rnn_kernel,
                         cudaFuncAttributeMaxDynamicSharedMemorySize, 65536);
    rnn_kernel<<<GRID, NTHREADS, 65536>>>(inp, A, h0, out);
}